// round 4
// baseline (speedup 1.0000x reference)
#include <cuda_runtime.h>
#include <cstdint>
#include <cstddef>
#include <math.h>

// ============================================================================
// Problem dims
// ============================================================================
#define PP   54
#define BBT  2048
#define DDIM 512

static constexpr size_t XT = (size_t)BBT * PP * DDIM;   // 56,623,104
static constexpr size_t WE = (size_t)PP * DDIM * DDIM;  // 14,155,776

static constexpr int BM = 128, BN = 256, BK = 32, STAGES = 4;
static constexpr int NTH = 256;
static constexpr int SM_STAGE = (BM + BN) * BK;            // floats per stage = 12288
static constexpr int SMEM_BYTES = SM_STAGE * STAGES * 4;   // 196608

// ============================================================================
// Device-global scratch (the allowed allocation mechanism)
// ============================================================================
__device__ __align__(16) float g_xr[XT];   // tf32-rounded x, layout [B,P,D]
__device__ __align__(16) float g_h[XT];    // gelu(h), tf32-rounded, layout [P,B,D]
__device__ __align__(16) float g_w1[WE];   // tf32-rounded W1 [P,D,D]
__device__ __align__(16) float g_w2[WE];   // tf32-rounded W2 [P,D,D]
__device__ float2 g_stats[(size_t)BBT * PP * 8];  // per-row, per-64col-slice (sum, sumsq)

// ============================================================================
// Helpers (all plain sm_80-era PTX: compiles for compute_103 without 'a')
// ============================================================================
__device__ __forceinline__ float tf32r(float x) {
    float r; asm("cvt.rna.tf32.f32 %0, %1;" : "=f"(r) : "f"(x)); return r;
}
__device__ __forceinline__ uint32_t s2u(const void* p) {
    uint32_t a;
    asm("{ .reg .u64 t; cvta.to.shared.u64 t, %1; cvt.u32.u64 %0, t; }" : "=r"(a) : "l"(p));
    return a;
}
__device__ __forceinline__ void cp16(uint32_t d, const void* s) {
    asm volatile("cp.async.cg.shared.global [%0], [%1], 16;" :: "r"(d), "l"(s));
}
__device__ __forceinline__ void cp_commit() { asm volatile("cp.async.commit_group;"); }
template <int N>
__device__ __forceinline__ void cp_wait() { asm volatile("cp.async.wait_group %0;" :: "n"(N)); }

__device__ __forceinline__ void mma8(float c[4], const float a[4], const float b[2]) {
    asm volatile(
        "mma.sync.aligned.m16n8k8.row.col.f32.tf32.tf32.f32 "
        "{%0,%1,%2,%3}, {%4,%5,%6,%7}, {%8,%9}, {%0,%1,%2,%3};"
        : "+f"(c[0]), "+f"(c[1]), "+f"(c[2]), "+f"(c[3])
        : "r"(__float_as_uint(a[0])), "r"(__float_as_uint(a[1])),
          "r"(__float_as_uint(a[2])), "r"(__float_as_uint(a[3])),
          "r"(__float_as_uint(b[0])), "r"(__float_as_uint(b[1])));
}

// ============================================================================
// Stage loader. SMEM element (row, k) lives at row*32 + (k ^ ((row&7)<<2)).
// 16B cp.async chunks: chunk' = chunk ^ (row&7)  (xor carries no bits -> exact).
// Conflict-free for both STS.128 and all fragment LDS patterns.
// ============================================================================
__device__ __forceinline__ void load_stage(uint32_t smu, int stage,
                                           const float* __restrict__ Ab, size_t Ars,
                                           const float* __restrict__ Bb,
                                           int k0, int tid) {
    uint32_t st = smu + stage * (SM_STAGE * 4);
#pragma unroll
    for (int t = 0; t < (BM * BK / 8) / NTH * 2; ++t) {  // 4 iters: 1024 chunks of A
        int idx = tid + t * NTH;
        int row = idx >> 3, seg = idx & 7;
        cp16(st + row * 128 + ((seg ^ (row & 7)) << 4),
             Ab + (size_t)row * Ars + k0 + seg * 4);
    }
    uint32_t stB = st + BM * BK * 4;
#pragma unroll
    for (int t = 0; t < 8; ++t) {                        // 2048 chunks of B
        int idx = tid + t * NTH;
        int row = idx >> 3, seg = idx & 7;
        cp16(stB + row * 128 + ((seg ^ (row & 7)) << 4),
             Bb + (size_t)row * DDIM + k0 + seg * 4);
    }
}

// ============================================================================
// Core: C[128x256] = A[128x512] * B[256x512]^T (both K-major, tf32)
// 8 warps as 2(m) x 4(n); warp tile 64x64; acc[4 mfrag][8 nfrag][4]
// ============================================================================
__device__ __forceinline__ void gemm_core(const float* __restrict__ Ab, size_t Ars,
                                          const float* __restrict__ Bb,
                                          float acc[4][8][4], float* smemf) {
    int tid = threadIdx.x;
    uint32_t smu = s2u(smemf);
#pragma unroll
    for (int s = 0; s < STAGES - 1; ++s) {
        load_stage(smu, s, Ab, Ars, Bb, s * BK, tid);
        cp_commit();
    }
    int lane = tid & 31, warp = tid >> 5;
    int wy = warp & 1, wx = warp >> 1;
    int q = lane >> 2, t4 = lane & 3;
    int sxo = q << 2;  // swizzle key: row&7 == q for every A-row/B-row this thread touches

    int rA[4], rB[8];
#pragma unroll
    for (int i = 0; i < 4; ++i) rA[i] = (wy * 64 + 16 * i + q) * BK;
#pragma unroll
    for (int j = 0; j < 8; ++j) rB[j] = BM * BK + (wx * 64 + 8 * j + q) * BK;

    int ld = STAGES - 1;
#pragma unroll 1
    for (int kc = 0; kc < DDIM / BK; ++kc) {
        cp_wait<STAGES - 2>();
        __syncthreads();  // stage kc visible to all; all warps done with stage (kc-1)
        if (ld < DDIM / BK) {
            load_stage(smu, ld & (STAGES - 1), Ab, Ars, Bb, ld * BK, tid);
            ++ld;
        }
        cp_commit();
        const float* sb = smemf + (kc & (STAGES - 1)) * SM_STAGE;
#pragma unroll
        for (int ks = 0; ks < 4; ++ks) {
            int c0 = (8 * ks + t4) ^ sxo;
            int c1 = (8 * ks + 4 + t4) ^ sxo;
            float a[4][4], b[8][2];
#pragma unroll
            for (int i = 0; i < 4; ++i) {
                a[i][0] = sb[rA[i] + c0];
                a[i][1] = sb[rA[i] + 8 * BK + c0];
                a[i][2] = sb[rA[i] + c1];
                a[i][3] = sb[rA[i] + 8 * BK + c1];
            }
#pragma unroll
            for (int j = 0; j < 8; ++j) {
                b[j][0] = sb[rB[j] + c0];
                b[j][1] = sb[rB[j] + c1];
            }
#pragma unroll
            for (int i = 0; i < 4; ++i)
#pragma unroll
                for (int j = 0; j < 8; ++j) mma8(acc[i][j], a[i], b[j]);
        }
    }
}

// ============================================================================
// GEMM1: h = gelu(x @ W1^T + b1) -> g_h [P,B,D] (tf32-rounded)
// ============================================================================
__global__ void __launch_bounds__(NTH, 1)
gemm1_kernel(const float* __restrict__ b1) {
    extern __shared__ float smemf[];
    int p = blockIdx.z, m0 = blockIdx.y * BM, n0 = blockIdx.x * BN;
    const float* Ab = g_xr + ((size_t)m0 * PP + p) * DDIM;
    const float* Bb = g_w1 + (size_t)p * DDIM * DDIM + (size_t)n0 * DDIM;

    float acc[4][8][4];
#pragma unroll
    for (int i = 0; i < 4; ++i)
#pragma unroll
        for (int j = 0; j < 8; ++j)
#pragma unroll
            for (int k = 0; k < 4; ++k) acc[i][j][k] = 0.0f;

    gemm_core(Ab, (size_t)PP * DDIM, Bb, acc, smemf);

    int lane = threadIdx.x & 31, warp = threadIdx.x >> 5;
    int wy = warp & 1, wx = warp >> 1, q = lane >> 2, t4 = lane & 3;
    const float* bias = b1 + p * DDIM + n0 + wx * 64;
#pragma unroll
    for (int i = 0; i < 4; ++i)
#pragma unroll
        for (int h = 0; h < 2; ++h) {
            int row = m0 + wy * 64 + 16 * i + q + 8 * h;
            float* hrow = g_h + ((size_t)p * BBT + row) * DDIM + n0 + wx * 64;
#pragma unroll
            for (int j = 0; j < 8; ++j) {
                int col = 8 * j + 2 * t4;
                float v0 = acc[i][j][2 * h]     + __ldg(bias + col);
                float v1 = acc[i][j][2 * h + 1] + __ldg(bias + col + 1);
                float g0 = 0.5f * v0 * (1.0f + erff(v0 * 0.70710678118654752f));
                float g1 = 0.5f * v1 * (1.0f + erff(v1 * 0.70710678118654752f));
                *reinterpret_cast<float2*>(hrow + col) = make_float2(tf32r(g0), tf32r(g1));
            }
        }
}

// ============================================================================
// GEMM2: d_out = h @ W2^T + b2 + x (unnormalized), plus per-slice LN stats
// ============================================================================
__global__ void __launch_bounds__(NTH, 1)
gemm2_kernel(const float* __restrict__ x, const float* __restrict__ b2,
             float* __restrict__ out) {
    extern __shared__ float smemf[];
    int p = blockIdx.z, m0 = blockIdx.y * BM, n0 = blockIdx.x * BN;
    const float* Ab = g_h + ((size_t)p * BBT + m0) * DDIM;
    const float* Bb = g_w2 + (size_t)p * DDIM * DDIM + (size_t)n0 * DDIM;

    float acc[4][8][4];
#pragma unroll
    for (int i = 0; i < 4; ++i)
#pragma unroll
        for (int j = 0; j < 8; ++j)
#pragma unroll
            for (int k = 0; k < 4; ++k) acc[i][j][k] = 0.0f;

    gemm_core(Ab, DDIM, Bb, acc, smemf);

    int lane = threadIdx.x & 31, warp = threadIdx.x >> 5;
    int wy = warp & 1, wx = warp >> 1, q = lane >> 2, t4 = lane & 3;
    const float* bias = b2 + p * DDIM + n0 + wx * 64;
    int slice = blockIdx.x * 4 + wx;  // 8 slices of 64 columns per output row
#pragma unroll
    for (int i = 0; i < 4; ++i)
#pragma unroll
        for (int h = 0; h < 2; ++h) {
            int row = m0 + wy * 64 + 16 * i + q + 8 * h;  // batch index b
            size_t ro = (size_t)row * PP + p;             // output row id
            const float* xr = x + ro * DDIM + n0 + wx * 64;
            float* orow = out + ro * DDIM + n0 + wx * 64;
            float s = 0.0f, ss = 0.0f;
#pragma unroll
            for (int j = 0; j < 8; ++j) {
                int col = 8 * j + 2 * t4;
                float v0 = acc[i][j][2 * h]     + __ldg(bias + col)     + __ldg(xr + col);
                float v1 = acc[i][j][2 * h + 1] + __ldg(bias + col + 1) + __ldg(xr + col + 1);
                *reinterpret_cast<float2*>(orow + col) = make_float2(v0, v1);
                s += v0 + v1;
                ss += v0 * v0 + v1 * v1;
            }
            s  += __shfl_xor_sync(0xffffffffu, s, 1);
            s  += __shfl_xor_sync(0xffffffffu, s, 2);
            ss += __shfl_xor_sync(0xffffffffu, ss, 1);
            ss += __shfl_xor_sync(0xffffffffu, ss, 2);
            if (t4 == 0) g_stats[ro * 8 + slice] = make_float2(s, ss);
        }
}

// ============================================================================
// LN finalize: normalize d_out in place using precomputed stats
// ============================================================================
__global__ void __launch_bounds__(256)
ln_kernel(float* __restrict__ out, const float* __restrict__ gamma,
          const float* __restrict__ beta) {
    int warp = threadIdx.x >> 5, lane = threadIdx.x & 31;
    size_t r = (size_t)blockIdx.x * 8 + warp;
    float s = 0.0f, ss = 0.0f;
    if (lane < 8) {
        float2 st = g_stats[r * 8 + lane];
        s = st.x; ss = st.y;
    }
    s  += __shfl_xor_sync(0xffffffffu, s, 1);
    s  += __shfl_xor_sync(0xffffffffu, s, 2);
    s  += __shfl_xor_sync(0xffffffffu, s, 4);
    ss += __shfl_xor_sync(0xffffffffu, ss, 1);
    ss += __shfl_xor_sync(0xffffffffu, ss, 2);
    ss += __shfl_xor_sync(0xffffffffu, ss, 4);
    s  = __shfl_sync(0xffffffffu, s, 0);
    ss = __shfl_sync(0xffffffffu, ss, 0);
    float mu = s * (1.0f / 512.0f);
    float rstd = rsqrtf(ss * (1.0f / 512.0f) - mu * mu + 1e-5f);

    float* row = out + r * DDIM;
#pragma unroll
    for (int c = 0; c < 4; ++c) {
        int idx = c * 128 + lane * 4;
        float4 v = *reinterpret_cast<float4*>(row + idx);
        float4 g = *reinterpret_cast<const float4*>(gamma + idx);
        float4 b = *reinterpret_cast<const float4*>(beta + idx);
        v.x = (v.x - mu) * rstd * g.x + b.x;
        v.y = (v.y - mu) * rstd * g.y + b.y;
        v.z = (v.z - mu) * rstd * g.z + b.z;
        v.w = (v.w - mu) * rstd * g.w + b.w;
        *reinterpret_cast<float4*>(row + idx) = v;
    }
}

// ============================================================================
// tf32 rounding converters
// ============================================================================
__global__ void cvt_x_kernel(const float4* __restrict__ x) {
    size_t n = XT / 4;
    size_t stride = (size_t)gridDim.x * blockDim.x;
    float4* dst = reinterpret_cast<float4*>(g_xr);
    for (size_t t = (size_t)blockIdx.x * blockDim.x + threadIdx.x; t < n; t += stride) {
        float4 v = x[t];
        v.x = tf32r(v.x); v.y = tf32r(v.y); v.z = tf32r(v.z); v.w = tf32r(v.w);
        dst[t] = v;
    }
}
__global__ void cvt_w_kernel(const float4* __restrict__ w1, const float4* __restrict__ w2) {
    size_t n = WE / 4;
    size_t stride = (size_t)gridDim.x * blockDim.x;
    float4* d1 = reinterpret_cast<float4*>(g_w1);
    float4* d2 = reinterpret_cast<float4*>(g_w2);
    for (size_t t = (size_t)blockIdx.x * blockDim.x + threadIdx.x; t < n; t += stride) {
        float4 v = w1[t];
        v.x = tf32r(v.x); v.y = tf32r(v.y); v.z = tf32r(v.z); v.w = tf32r(v.w);
        d1[t] = v;
        v = w2[t];
        v.x = tf32r(v.x); v.y = tf32r(v.y); v.z = tf32r(v.z); v.w = tf32r(v.w);
        d2[t] = v;
    }
}

// ============================================================================
// kernel_launch
// ============================================================================
extern "C" void kernel_launch(void* const* d_in, const int* in_sizes, int n_in,
                              void* d_out, int out_size) {
    const float* x     = (const float*)d_in[0];
    const float* W1    = (const float*)d_in[1];
    const float* b1    = (const float*)d_in[2];
    const float* W2    = (const float*)d_in[3];
    const float* b2    = (const float*)d_in[4];
    const float* gamma = (const float*)d_in[5];
    const float* beta  = (const float*)d_in[6];
    float* out = (float*)d_out;

    cudaFuncSetAttribute(gemm1_kernel, cudaFuncAttributeMaxDynamicSharedMemorySize, SMEM_BYTES);
    cudaFuncSetAttribute(gemm2_kernel, cudaFuncAttributeMaxDynamicSharedMemorySize, SMEM_BYTES);

    cvt_x_kernel<<<1184, 256>>>(reinterpret_cast<const float4*>(x));
    cvt_w_kernel<<<1184, 256>>>(reinterpret_cast<const float4*>(W1),
                                reinterpret_cast<const float4*>(W2));

    // x fastest = n-tile: adjacent CTAs share the A tile; one patch's W (1MB) stays L2-hot
    dim3 grid(BN == 256 ? 2 : 4, BBT / BM, PP);  // (2, 16, 54)
    gemm1_kernel<<<grid, NTH, SMEM_BYTES>>>(b1);
    gemm2_kernel<<<grid, NTH, SMEM_BYTES>>>(x, b2, out);

    ln_kernel<<<(BBT * PP) / 8, 256>>>(out, gamma, beta);
}